// round 4
// baseline (speedup 1.0000x reference)
#include <cuda_runtime.h>
#include <cuda_bf16.h>
#include <stdint.h>

#define NROWS 16384
#define DIM   768
#define NLAT  5000
#define NLATP 5120
#define CHARS 8

// ---- GEMM tiling ----
#define BM 128
#define BN 64
#define BK 32
#define NST 4
#define ASTB (BM*BK*2)           // 8 KB A stage
#define BSTB (BN*BK*2)           // 4 KB B stage
#define STB  (ASTB+BSTB)         // 12 KB per stage
#define SMEM_TOTAL (NST*STB)     // 48 KB

// ---------------- scratch ----------------
__device__ int g_is64;
__device__ __align__(128) __nv_bfloat16 g_L [(size_t)NLATP*DIM];   // latent [5120,768] K-major, pad rows 0
__device__ __align__(128) __nv_bfloat16 g_LT[(size_t)DIM*NLATP];   // latent^T [768,5120] K-major, pad cols 0
__device__ __align__(128) float         g_E [(size_t)NROWS*DIM];   // lang_emb fp32
__device__ __align__(128) __nv_bfloat16 g_Eb[(size_t)NROWS*DIM];   // lang_emb bf16
__device__ __align__(128) float         g_S [(size_t)NROWS*NLATP]; // scores fp32
__device__ __align__(128) __nv_bfloat16 g_Dist[(size_t)NROWS*NLATP];

// ---------------- helpers ----------------
__device__ __forceinline__ uint32_t smem_u32(const void* p) {
    uint32_t a;
    asm("{ .reg .u64 t; cvta.to.shared.u64 t, %1; cvt.u32.u64 %0, t; }" : "=r"(a) : "l"(p));
    return a;
}
__device__ __forceinline__ uint32_t swz(uint32_t off) {        // 64B-row swizzle
    return off ^ (((off >> 7) & 3u) << 4);
}
#define CP_ASYNC16(dst, src) \
    asm volatile("cp.async.cg.shared.global [%0], [%1], 16;" :: "r"(dst), "l"(src) : "memory")
#define CP_COMMIT() asm volatile("cp.async.commit_group;" ::: "memory")
#define CP_WAIT2()  asm volatile("cp.async.wait_group 2;"  ::: "memory")

#define LDMX4(r0,r1,r2,r3,a) \
    asm volatile("ldmatrix.sync.aligned.m8n8.x4.shared.b16 {%0,%1,%2,%3}, [%4];" \
        : "=r"(r0), "=r"(r1), "=r"(r2), "=r"(r3) : "r"(a))

#define MMA16816(d, a0,a1,a2,a3, b0,b1) \
    asm volatile("mma.sync.aligned.m16n8k16.row.col.f32.bf16.bf16.f32 " \
        "{%0,%1,%2,%3}, {%4,%5,%6,%7}, {%8,%9}, {%0,%1,%2,%3};" \
        : "+f"((d)[0]), "+f"((d)[1]), "+f"((d)[2]), "+f"((d)[3]) \
        : "r"(a0), "r"(a1), "r"(a2), "r"(a3), "r"(b0), "r"(b1))

// ---------------- small kernels ----------------
__global__ void detect_kernel(const int* __restrict__ x32) {
    if (threadIdx.x == 0 && blockIdx.x == 0) {
        int is64 = 1;
        for (int i = 1; i < 128; i += 2)
            if (x32[i] != 0) { is64 = 0; break; }
        g_is64 = is64;
    }
}

__global__ void conv_latent_kernel(const float* __restrict__ L) {
    int idx = blockIdx.x * 256 + threadIdx.x;
    if (idx < NLATP * DIM) {
        int r = idx / DIM;
        float v = (r < NLAT) ? L[idx] : 0.0f;
        g_L[idx] = __float2bfloat16(v);
    }
}

__global__ void transpose_latent_kernel(const float* __restrict__ L) {
    __shared__ float t[32][33];
    int k0 = blockIdx.x * 32, d0 = blockIdx.y * 32;
    #pragma unroll
    for (int i = 0; i < 4; i++) {
        int k = k0 + threadIdx.y + 8 * i;
        t[threadIdx.y + 8 * i][threadIdx.x] =
            (k < NLAT) ? L[(size_t)k * DIM + d0 + threadIdx.x] : 0.0f;
    }
    __syncthreads();
    #pragma unroll
    for (int i = 0; i < 4; i++) {
        int d = d0 + threadIdx.y + 8 * i;
        g_LT[(size_t)d * NLATP + k0 + threadIdx.x] =
            __float2bfloat16(t[threadIdx.x][threadIdx.y + 8 * i]);
    }
}

__global__ void embed_kernel(const void* __restrict__ xv, const float* __restrict__ ce) {
    __shared__ int ids[CHARS];
    __shared__ float s_inv;
    int n = blockIdx.x;
    if (threadIdx.x < CHARS) {
        int id;
        if (g_is64) id = (int)((const long long*)xv)[(size_t)n * CHARS + threadIdx.x];
        else        id = ((const int*)xv)[(size_t)n * CHARS + threadIdx.x];
        ids[threadIdx.x] = id;
    }
    __syncthreads();
    if (threadIdx.x == 0) {
        int c = 0;
        #pragma unroll
        for (int i = 0; i < CHARS; i++) c += (ids[i] != 0);
        if (c < 1) c = 1;
        s_inv = 1.0f / (float)c;
    }
    __syncthreads();
    float inv = s_inv;
    for (int d = threadIdx.x; d < DIM; d += 256) {
        float s = 0.0f;
        #pragma unroll
        for (int c = 0; c < CHARS; c++) {
            int id = ids[c];
            if (id != 0) s += ce[(size_t)id * DIM + d];
        }
        float v = tanhf(s * inv);
        size_t o = (size_t)n * DIM + d;
        g_E[o]  = v;
        g_Eb[o] = __float2bfloat16(v);
    }
}

__global__ void softmax_kernel() {
    __shared__ float sc[NLAT];
    __shared__ float red[256];
    int n = blockIdx.x, t = threadIdx.x;
    const float* s = g_S + (size_t)n * NLATP;

    float m = -1e30f;
    for (int i = t; i < NLAT; i += 256) { float v = s[i]; sc[i] = v; m = fmaxf(m, v); }
    red[t] = m; __syncthreads();
    for (int off = 128; off; off >>= 1) {
        if (t < off) red[t] = fmaxf(red[t], red[t + off]);
        __syncthreads();
    }
    m = red[0]; __syncthreads();

    float sum = 0.0f;
    for (int i = t; i < NLAT; i += 256) sum += __expf(sc[i] - m);
    red[t] = sum; __syncthreads();
    for (int off = 128; off; off >>= 1) {
        if (t < off) red[t] += red[t + off];
        __syncthreads();
    }
    float inv = 1.0f / red[0];

    __nv_bfloat16* d = g_Dist + (size_t)n * NLATP;
    for (int i = t; i < NLAT; i += 256) d[i] = __float2bfloat16(__expf(sc[i] - m) * inv);
    for (int i = NLAT + t; i < NLATP; i += 256) d[i] = __float2bfloat16(0.0f);
}

// ---------------- pipelined mma.sync GEMM ----------------
// C[BM,BN] = A[M,K] * B[N,K]^T, both K-major bf16. Warp tile 32x32 (acc = 32 regs).
// mode 1: C -> g_S (fp32 scores)
// mode 2: out = g_E + C with special-token override
__global__ __launch_bounds__(256, 2) void gemm_mma(
    const __nv_bfloat16* __restrict__ A, size_t lda,
    const __nv_bfloat16* __restrict__ B, size_t ldb,
    int nchunks, int mode,
    const void* __restrict__ xv, const float* __restrict__ ce,
    float* __restrict__ out)
{
    extern __shared__ char smem[];
    uint32_t sbase = smem_u32(smem);
    int tid = threadIdx.x, lane = tid & 31, wid = tid >> 5;
    int warp_m = wid >> 1, warp_n = wid & 1;
    size_t bm = (size_t)blockIdx.y * BM, bn = (size_t)blockIdx.x * BN;

    // cp.async source mapping: thread -> (row = tid>>2 [+64 for A], 16B chunk = tid&3)
    int ld_row = tid >> 2;
    int ld_c   = tid & 3;
    const char* agp = (const char*)(A + (bm + (size_t)ld_row) * lda) + ld_c * 16;
    const char* bgp = (const char*)(B + (bn + (size_t)ld_row) * ldb) + ld_c * 16;
    size_t astep = 64 * lda * 2;
    uint32_t soff  = swz((uint32_t)ld_row * 64 + (uint32_t)ld_c * 16);
    uint32_t soff2 = swz((uint32_t)(ld_row + 64) * 64 + (uint32_t)ld_c * 16);

    // ldmatrix lane addressing
    int fidx = lane & 7;
    int a_row0 = warp_m * 32 + ((lane >> 3) & 1) * 8 + fidx;  // + mt*16
    int a_cb   = lane >> 4;
    int b_row0 = warp_n * 32 + ((lane >> 4) << 3) + fidx;     // + nt*16
    int b_cb   = (lane >> 3) & 1;

    float acc[2][4][4];
    #pragma unroll
    for (int i = 0; i < 2; i++)
        #pragma unroll
        for (int j = 0; j < 4; j++)
            #pragma unroll
            for (int q = 0; q < 4; q++) acc[i][j][q] = 0.0f;

    // prologue
    #pragma unroll
    for (int s = 0; s < NST - 1; s++) {
        uint32_t sa = sbase + s * STB, sb = sa + ASTB;
        size_t koff = (size_t)s * BK * 2;
        CP_ASYNC16(sa + soff,  agp + koff);
        CP_ASYNC16(sa + soff2, agp + astep + koff);
        CP_ASYNC16(sb + soff,  bgp + koff);
        CP_COMMIT();
    }

    for (int i = 0; i < nchunks; i++) {
        CP_WAIT2();
        __syncthreads();

        int pf = i + NST - 1;
        if (pf < nchunks) {
            int s = pf & (NST - 1);
            uint32_t sa = sbase + s * STB, sb = sa + ASTB;
            size_t koff = (size_t)pf * BK * 2;
            CP_ASYNC16(sa + soff,  agp + koff);
            CP_ASYNC16(sa + soff2, agp + astep + koff);
            CP_ASYNC16(sb + soff,  bgp + koff);
        }
        CP_COMMIT();

        uint32_t sa = sbase + (i & (NST - 1)) * STB, sb = sa + ASTB;
        #pragma unroll
        for (int ks = 0; ks < 2; ks++) {
            uint32_t af[2][4], bf[2][4];
            #pragma unroll
            for (int mt = 0; mt < 2; mt++) {
                int row = a_row0 + mt * 16;
                uint32_t ad = sa + swz((uint32_t)row * 64 + (uint32_t)(ks * 2 + a_cb) * 16);
                LDMX4(af[mt][0], af[mt][1], af[mt][2], af[mt][3], ad);
            }
            #pragma unroll
            for (int nt = 0; nt < 2; nt++) {
                int row = b_row0 + nt * 16;
                uint32_t bd = sb + swz((uint32_t)row * 64 + (uint32_t)(ks * 2 + b_cb) * 16);
                LDMX4(bf[nt][0], bf[nt][1], bf[nt][2], bf[nt][3], bd);
            }
            #pragma unroll
            for (int mt = 0; mt < 2; mt++)
                #pragma unroll
                for (int nt = 0; nt < 2; nt++) {
                    MMA16816(acc[mt][2 * nt],     af[mt][0], af[mt][1], af[mt][2], af[mt][3],
                             bf[nt][0], bf[nt][1]);
                    MMA16816(acc[mt][2 * nt + 1], af[mt][0], af[mt][1], af[mt][2], af[mt][3],
                             bf[nt][2], bf[nt][3]);
                }
        }
    }

    // ---- epilogue ----
    int rbase = warp_m * 32 + (lane >> 2);
    int cbase = warp_n * 32 + (lane & 3) * 2;
    if (mode == 1) {
        #pragma unroll
        for (int mt = 0; mt < 2; mt++)
            #pragma unroll
            for (int h = 0; h < 2; h++) {
                size_t row = bm + rbase + mt * 16 + h * 8;
                float* dst = g_S + row * NLATP + bn + cbase;
                #pragma unroll
                for (int nt = 0; nt < 4; nt++)
                    *(float2*)(dst + nt * 8) =
                        make_float2(acc[mt][nt][2 * h], acc[mt][nt][2 * h + 1]);
            }
    } else {
        #pragma unroll
        for (int mt = 0; mt < 2; mt++)
            #pragma unroll
            for (int h = 0; h < 2; h++) {
                size_t row = bm + rbase + mt * 16 + h * 8;
                int first;
                if (g_is64) first = (int)((const long long*)xv)[row * CHARS];
                else        first = ((const int*)xv)[row * CHARS];
                size_t cb = bn + cbase;
                float* dst = out + row * DIM + cb;
                if (first < 4) {
                    const float* cp = ce + (size_t)first * DIM + cb;
                    #pragma unroll
                    for (int nt = 0; nt < 4; nt++)
                        *(float2*)(dst + nt * 8) = make_float2(cp[nt * 8], cp[nt * 8 + 1]);
                } else {
                    const float* ep = g_E + row * DIM + cb;
                    #pragma unroll
                    for (int nt = 0; nt < 4; nt++)
                        *(float2*)(dst + nt * 8) =
                            make_float2(ep[nt * 8]     + acc[mt][nt][2 * h],
                                        ep[nt * 8 + 1] + acc[mt][nt][2 * h + 1]);
                }
            }
    }
}

// ---------------- launch ----------------
extern "C" void kernel_launch(void* const* d_in, const int* in_sizes, int n_in,
                              void* d_out, int out_size) {
    const void*  x  = d_in[0];
    const float* ce = (const float*)d_in[1];
    const float* lm = (const float*)d_in[2];
    float* out = (float*)d_out;

    cudaFuncSetAttribute(gemm_mma, cudaFuncAttributeMaxDynamicSharedMemorySize, SMEM_TOTAL);

    detect_kernel<<<1, 32>>>((const int*)x);
    conv_latent_kernel<<<(NLATP * DIM + 255) / 256, 256>>>(lm);
    {
        dim3 blk(32, 8), grd(NLATP / 32, DIM / 32);
        transpose_latent_kernel<<<grd, blk>>>(lm);
    }
    embed_kernel<<<NROWS, 256>>>(x, ce);

    // GEMM1: scores = Eb[16384,768] * L[5120,768]^T
    {
        dim3 grid(NLATP / BN, NROWS / BM);
        gemm_mma<<<grid, 256, SMEM_TOTAL>>>(g_Eb, (size_t)DIM, g_L, (size_t)DIM,
                                            DIM / BK, 1, x, ce, nullptr);
    }

    softmax_kernel<<<NROWS, 256>>>();

    // GEMM2 (+fused epilogue): out = E + Dist[16384,5120] * LT[768,5120]^T
    {
        dim3 grid(DIM / BN, NROWS / BM);
        gemm_mma<<<grid, 256, SMEM_TOTAL>>>(g_Dist, (size_t)NLATP, g_LT, (size_t)NLATP,
                                            NLATP / BK, 2, x, ce, out);
    }
}